// round 15
// baseline (speedup 1.0000x reference)
#include <cuda_runtime.h>
#include <cuda_fp16.h>
#include <cstdint>

#define NMAX 100000
#define EMAX 3200000
#define F 64
#define GMAX 64
#define PAD 128        // bucket capacity per node (max realistic degree ~60)
#define PADSH 7
#define XSTR 72        // smem row stride in halves (144B: conflict-free ldmatrix)
#define GW 8           // gather warps (nodes) per block

struct __align__(8) EdgeT { int s; float w; };

// Scratch (device globals — no allocation allowed)
__device__ int   g_cnt_n[NMAX];                      // per-node fill cursor == degree
__device__ float g_scale[NMAX];                      // 1/(sum_w*(deg+1)), layer-1 byproduct
__device__ __align__(16) EdgeT g_csr[NMAX * PAD];    // padded buckets {src, w}
__device__ __align__(16) __half g_hf[NMAX * F];      // fp16 table A (H0 / h1 / h2)
__device__ __align__(16) __half g_y[NMAX * F];       // fp16 table B (Y = H@W)
__device__ __align__(16) float  g_pool[GMAX * F];
__device__ float g_cnt[GMAX];

__device__ __forceinline__ __half2 u2h2(unsigned u) {
    return *reinterpret_cast<__half2*>(&u);
}

// ---------------------------------------------------------------------------
// Fused prologue: zero cursors/pool and convert input to fp16 table
// ---------------------------------------------------------------------------
__global__ void k_prep(const float* __restrict__ in, int n, int g) {
    int i = blockIdx.x * blockDim.x + threadIdx.x;
    int total4 = n * 16;
    if (i < total4) {
        float4 v = reinterpret_cast<const float4*>(in)[i];
        __half2 lo = __floats2half2_rn(v.x, v.y);
        __half2 hi = __floats2half2_rn(v.z, v.w);
        uint2 pk;
        pk.x = *reinterpret_cast<unsigned*>(&lo);
        pk.y = *reinterpret_cast<unsigned*>(&hi);
        reinterpret_cast<uint2*>(g_hf)[i] = pk;
    }
    if (i < n) g_cnt_n[i] = 0;
    if (i < g * F) g_pool[i] = 0.f;
    if (i < g) g_cnt[i] = 0.f;
}

// ---------------------------------------------------------------------------
// Bucket fill: 8 edges per thread. Cursor atomic doubles as degree count.
// ---------------------------------------------------------------------------
__global__ void k_fill(const float* __restrict__ ew, const int* __restrict__ src,
                       const int* __restrict__ dst, int e8) {
    int i = blockIdx.x * blockDim.x + threadIdx.x;
    if (i >= e8) return;
    int4   sa = reinterpret_cast<const int4*>(src)[2 * i];
    int4   sb = reinterpret_cast<const int4*>(src)[2 * i + 1];
    int4   da = reinterpret_cast<const int4*>(dst)[2 * i];
    int4   db = reinterpret_cast<const int4*>(dst)[2 * i + 1];
    float4 wa = reinterpret_cast<const float4*>(ew)[2 * i];
    float4 wb = reinterpret_cast<const float4*>(ew)[2 * i + 1];

    int p0 = atomicAdd(&g_cnt_n[da.x], 1);
    int p1 = atomicAdd(&g_cnt_n[da.y], 1);
    int p2 = atomicAdd(&g_cnt_n[da.z], 1);
    int p3 = atomicAdd(&g_cnt_n[da.w], 1);
    int p4 = atomicAdd(&g_cnt_n[db.x], 1);
    int p5 = atomicAdd(&g_cnt_n[db.y], 1);
    int p6 = atomicAdd(&g_cnt_n[db.z], 1);
    int p7 = atomicAdd(&g_cnt_n[db.w], 1);

    EdgeT r;
    r.s = sa.x; r.w = wa.x; g_csr[(da.x << PADSH) + p0] = r;
    r.s = sa.y; r.w = wa.y; g_csr[(da.y << PADSH) + p1] = r;
    r.s = sa.z; r.w = wa.z; g_csr[(da.z << PADSH) + p2] = r;
    r.s = sa.w; r.w = wa.w; g_csr[(da.w << PADSH) + p3] = r;
    r.s = sb.x; r.w = wb.x; g_csr[(db.x << PADSH) + p4] = r;
    r.s = sb.y; r.w = wb.y; g_csr[(db.y << PADSH) + p5] = r;
    r.s = sb.z; r.w = wb.z; g_csr[(db.z << PADSH) + p6] = r;
    r.s = sb.w; r.w = wb.w; g_csr[(db.w << PADSH) + p7] = r;
}

// tail edges (e not divisible by 8)
__global__ void k_fill_tail(const float* __restrict__ ew, const int* __restrict__ src,
                            const int* __restrict__ dst, int lo, int e) {
    int i = lo + blockIdx.x * blockDim.x + threadIdx.x;
    if (i < e) {
        int d = dst[i];
        int pos = atomicAdd(&g_cnt_n[d], 1);
        EdgeT rec;
        rec.s = src[i];
        rec.w = ew[i];
        g_csr[(d << PADSH) + pos] = rec;
    }
}

// ---------------------------------------------------------------------------
// Tensor-core GEMM: Y = X @ W (fp16 in, fp16 out, fp32 accum, no bias/relu).
// 64x64 tile, 128 threads (4 warps x 16 rows). mma.sync m16n8k16.
// ---------------------------------------------------------------------------
__global__ void __launch_bounds__(128) k_gemm(const __half* __restrict__ x,
                                              const float* __restrict__ W,
                                              __half* __restrict__ y, int n) {
    __shared__ __half Xs[64 * XSTR];
    __shared__ __half Wsm[64 * XSTR];

    int t = threadIdx.x;
    int lane = t & 31;
    int warp = t >> 5;
    int base = blockIdx.x * 64;

    const uint4* xh = reinterpret_cast<const uint4*>(x);
    #pragma unroll
    for (int j = 0; j < 4; j++) {
        int f = t + 128 * j;
        int nl = f >> 3;
        int k8 = f & 7;
        int gn = base + nl;
        uint4 v = make_uint4(0u, 0u, 0u, 0u);
        if (gn < n) v = xh[gn * 8 + k8];
        *reinterpret_cast<uint4*>(&Xs[nl * XSTR + k8 * 8]) = v;
    }
    #pragma unroll
    for (int j = 0; j < 8; j++) {
        int f = t + 128 * j;
        int k = f >> 4;
        int n4 = f & 15;
        float4 wv = reinterpret_cast<const float4*>(W)[k * 16 + n4];
        __half2 lo = __floats2half2_rn(wv.x, wv.y);
        __half2 hi = __floats2half2_rn(wv.z, wv.w);
        uint2 pk;
        pk.x = *reinterpret_cast<unsigned*>(&lo);
        pk.y = *reinterpret_cast<unsigned*>(&hi);
        *reinterpret_cast<uint2*>(&Wsm[k * XSTR + n4 * 4]) = pk;
    }
    __syncthreads();

    float acc[8][4];
    #pragma unroll
    for (int nt = 0; nt < 8; nt++)
        #pragma unroll
        for (int i = 0; i < 4; i++) acc[nt][i] = 0.f;

    uint32_t xs_base = (uint32_t)__cvta_generic_to_shared(Xs);
    uint32_t ws_base = (uint32_t)__cvta_generic_to_shared(Wsm);

    int arow = warp * 16 + (lane & 15);
    uint32_t a_off = xs_base + (uint32_t)(arow * XSTR * 2 + (lane >> 4) * 16);
    int brow = lane & 15;

    #pragma unroll
    for (int kit = 0; kit < 4; kit++) {
        uint32_t a0, a1, a2, a3;
        asm volatile("ldmatrix.sync.aligned.m8n8.x4.shared.b16 {%0,%1,%2,%3}, [%4];"
                     : "=r"(a0), "=r"(a1), "=r"(a2), "=r"(a3)
                     : "r"(a_off + kit * 32));
        uint32_t b_base = ws_base + (uint32_t)((kit * 16 + brow) * XSTR * 2);
        #pragma unroll
        for (int nt = 0; nt < 8; nt++) {
            uint32_t b0, b1;
            asm volatile("ldmatrix.sync.aligned.m8n8.x2.trans.shared.b16 {%0,%1}, [%2];"
                         : "=r"(b0), "=r"(b1)
                         : "r"(b_base + nt * 16));
            asm volatile("mma.sync.aligned.m16n8k16.row.col.f32.f16.f16.f32 "
                         "{%0,%1,%2,%3}, {%4,%5,%6,%7}, {%8,%9}, {%0,%1,%2,%3};"
                         : "+f"(acc[nt][0]), "+f"(acc[nt][1]),
                           "+f"(acc[nt][2]), "+f"(acc[nt][3])
                         : "r"(a0), "r"(a1), "r"(a2), "r"(a3), "r"(b0), "r"(b1));
        }
    }

    int drow = warp * 16 + (lane >> 2);
    int dcolh = (lane & 3);
    #pragma unroll
    for (int nt = 0; nt < 8; nt++) {
        int col2 = nt * 4 + dcolh;
        int gn0 = base + drow;
        int gn1 = gn0 + 8;
        if (gn0 < n) {
            __half2 p = __floats2half2_rn(acc[nt][0], acc[nt][1]);
            reinterpret_cast<unsigned*>(y)[gn0 * 32 + col2] = *reinterpret_cast<unsigned*>(&p);
        }
        if (gn1 < n) {
            __half2 p = __floats2half2_rn(acc[nt][2], acc[nt][3]);
            reinterpret_cast<unsigned*>(y)[gn1 * 32 + col2] = *reinterpret_cast<unsigned*>(&p);
        }
    }
}

// ---------------------------------------------------------------------------
// Tensor-core gather: warp per dst node. Per 16-edge chunk:
//   stage 16 source rows (zero-padded) into smem, build a broadcast A
//   fragment from the fp16 edge weights, ldmatrix.x2.trans the rows and
//   mma-accumulate D[16x64] (all rows identical; row 0 used).
// Epilogue (lanes 0-3): out = relu(sc*aggr + Y[self]/(deg+1) + b), fp16.
// FIRST: accumulate sum_w (fp32), store g_scale = 1/(sum_w*(deg+1)).
// ---------------------------------------------------------------------------
template <bool FIRST>
__global__ void __launch_bounds__(256) k_gather(const __half* __restrict__ ytab,
                                                const float* __restrict__ b,
                                                __half* __restrict__ out, int n) {
    __shared__ __align__(16) __half Bs[GW][16 * XSTR];

    int lane = threadIdx.x & 31;
    int warp = threadIdx.x >> 5;
    int node = blockIdx.x * GW + warp;
    if (node >= n) return;

    int cnt = g_cnt_n[node];
    const EdgeT* row = g_csr + (node << PADSH);

    int lr = lane >> 3;        // staging row group (0..3)
    int lc = lane & 7;         // 16B chunk within row (0..7)
    int c4 = lane & 3;         // A-fragment k-pair selector

    float acc[8][4];
    #pragma unroll
    for (int nt = 0; nt < 8; nt++)
        #pragma unroll
        for (int i = 0; i < 4; i++) acc[nt][i] = 0.f;
    float sw = 0.f;

    uint32_t sbase = (uint32_t)__cvta_generic_to_shared(&Bs[warp][0]);
    const char* ybase = reinterpret_cast<const char*>(ytab);

    for (int k0 = 0; k0 < cnt; k0 += 16) {
        __syncwarp();   // previous chunk's ldmatrix reads complete before overwrite

        // stage 16 rows (4 per iteration), zero-pad past cnt
        #pragma unroll
        for (int it = 0; it < 4; it++) {
            int r = it * 4 + lr;
            int k = k0 + r;
            uint4 v = make_uint4(0u, 0u, 0u, 0u);
            if (k < cnt) {
                int s = row[k].s;
                v = *reinterpret_cast<const uint4*>(ybase + s * 128 + lc * 16);
            }
            *reinterpret_cast<uint4*>(
                reinterpret_cast<char*>(&Bs[warp][0]) + r * 144 + lc * 16) = v;
        }

        // A fragment: broadcast weight row (zero-padded), fp32 -> f16x2
        int ka = k0 + 2 * c4;
        float w0 = (ka     < cnt) ? row[ka].w     : 0.f;
        float w1 = (ka + 1 < cnt) ? row[ka + 1].w : 0.f;
        float w2 = (ka + 8 < cnt) ? row[ka + 8].w : 0.f;
        float w3 = (ka + 9 < cnt) ? row[ka + 9].w : 0.f;
        if (FIRST) sw += (w0 + w1) + (w2 + w3);
        uint32_t a01, a23;
        asm("cvt.rn.f16x2.f32 %0, %1, %2;" : "=r"(a01) : "f"(w1), "f"(w0));
        asm("cvt.rn.f16x2.f32 %0, %1, %2;" : "=r"(a23) : "f"(w3), "f"(w2));

        __syncwarp();   // staging visible to ldmatrix

        uint32_t baddr = sbase + (uint32_t)((lane & 15) * 144);
        #pragma unroll
        for (int nt = 0; nt < 8; nt++) {
            uint32_t b0, b1;
            asm volatile("ldmatrix.sync.aligned.m8n8.x2.trans.shared.b16 {%0,%1}, [%2];"
                         : "=r"(b0), "=r"(b1)
                         : "r"(baddr + nt * 16));
            asm volatile("mma.sync.aligned.m16n8k16.row.col.f32.f16.f16.f32 "
                         "{%0,%1,%2,%3}, {%4,%5,%6,%7}, {%8,%9}, {%0,%1,%2,%3};"
                         : "+f"(acc[nt][0]), "+f"(acc[nt][1]),
                           "+f"(acc[nt][2]), "+f"(acc[nt][3])
                         : "r"(a01), "r"(a01), "r"(a23), "r"(a23), "r"(b0), "r"(b1));
        }
    }

    if (FIRST) {
        // lanes with same (lane&3) hold identical partial sums; reduce over c4
        sw += __shfl_xor_sync(0xffffffffu, sw, 1);
        sw += __shfl_xor_sync(0xffffffffu, sw, 2);
    }

    float inv = 1.0f / ((float)cnt + 1.0f);
    float sc;
    if (FIRST) {
        sc = (cnt > 0) ? (inv / sw) : 0.f;
        if (lane == 0) g_scale[node] = sc;
    } else {
        sc = g_scale[node];
    }

    // D row 0 lives on lanes 0-3: acc[nt][0],acc[nt][1] = cols 8nt+2*lane, +1
    if (lane < 4) {
        const unsigned* yp = reinterpret_cast<const unsigned*>(ytab);
        const float2* bp = reinterpret_cast<const float2*>(b);
        #pragma unroll
        for (int nt = 0; nt < 8; nt++) {
            int idx2 = nt * 4 + lane;               // half2 index within row
            float2 yself = __half22float2(u2h2(yp[node * 32 + idx2]));
            float2 bv = bp[idx2];
            float o0 = fmaxf(fmaf(acc[nt][0], sc, fmaf(yself.x, inv, bv.x)), 0.f);
            float o1 = fmaxf(fmaf(acc[nt][1], sc, fmaf(yself.y, inv, bv.y)), 0.f);
            __half2 p = __floats2half2_rn(o0, o1);
            reinterpret_cast<unsigned*>(out)[node * 32 + idx2] =
                *reinterpret_cast<unsigned*>(&p);
        }
    }
}

// ---------------------------------------------------------------------------
// Graph pooling on fp16 table: graph_ids sorted -> register run accumulation.
// ---------------------------------------------------------------------------
__global__ void k_pool(const __half* __restrict__ h, const int* __restrict__ gid, int n) {
    int wid = (blockIdx.x * blockDim.x + threadIdx.x) >> 5;
    int lane = threadIdx.x & 31;
    int nwarps = (gridDim.x * blockDim.x) >> 5;
    int chunk = (n + nwarps - 1) / nwarps;
    int start = wid * chunk;
    int end = min(start + chunk, n);
    if (start >= end) return;

    const unsigned* hp = reinterpret_cast<const unsigned*>(h);

    int cur = -1;
    float s0 = 0.f, s1 = 0.f, c = 0.f;
    for (int node = start; node < end; node++) {
        int g = gid[node];
        if (g != cur) {
            if (cur >= 0) {
                atomicAdd(&g_pool[cur * F + 2 * lane], s0);
                atomicAdd(&g_pool[cur * F + 2 * lane + 1], s1);
                if (lane == 0) atomicAdd(&g_cnt[cur], c);
            }
            cur = g; s0 = s1 = 0.f; c = 0.f;
        }
        float2 v = __half22float2(u2h2(hp[node * 32 + lane]));
        s0 += v.x;
        s1 += v.y;
        c += 1.f;
    }
    if (cur >= 0) {
        atomicAdd(&g_pool[cur * F + 2 * lane], s0);
        atomicAdd(&g_pool[cur * F + 2 * lane + 1], s1);
        if (lane == 0) atomicAdd(&g_cnt[cur], c);
    }
}

// ---------------------------------------------------------------------------
__global__ void k_final(const float* __restrict__ Wc, const float* __restrict__ bc,
                        float* __restrict__ out, int g) {
    int t = threadIdx.x;
    if (t >= g * 2) return;
    int gi = t >> 1;
    int c = t & 1;
    float inv = 1.0f / fmaxf(g_cnt[gi], 1.0f);
    float s = bc[c];
    #pragma unroll
    for (int f = 0; f < F; f++)
        s = fmaf(g_pool[gi * F + f] * inv, Wc[f * 2 + c], s);
    out[t] = s;
}

// ---------------------------------------------------------------------------
extern "C" void kernel_launch(void* const* d_in, const int* in_sizes, int n_in,
                              void* d_out, int out_size) {
    const float* in_feat = (const float*)d_in[0];
    const float* ew      = (const float*)d_in[1];
    const float* W1      = (const float*)d_in[2];
    const float* b1      = (const float*)d_in[3];
    const float* W2      = (const float*)d_in[4];
    const float* b2      = (const float*)d_in[5];
    const float* Wc      = (const float*)d_in[6];
    const float* bc      = (const float*)d_in[7];
    const int*   src     = (const int*)d_in[8];
    const int*   dst     = (const int*)d_in[9];
    const int*   gid     = (const int*)d_in[10];

    int n = in_sizes[0] / F;
    int e = in_sizes[1];
    int g = out_size / 2;

    void *p_hf = nullptr, *p_y = nullptr;
    cudaGetSymbolAddress(&p_hf, g_hf);
    cudaGetSymbolAddress(&p_y, g_y);
    __half* hf = (__half*)p_hf;
    __half* yb = (__half*)p_y;

    int e8 = e >> 3;
    int gblocks = (n + GW - 1) / GW;
    int tiles = (n + 63) / 64;

    // prologue: fused zero+cvt, then fill buckets
    k_prep<<<(n * 16 + 255) / 256, 256>>>(in_feat, n, g);
    k_fill<<<(e8 + 255) / 256, 256>>>(ew, src, dst, e8);
    if (e & 7)
        k_fill_tail<<<1, 256>>>(ew, src, dst, e8 * 8, e);

    // layer 1: Y1 = H0@W1 (HMMA), then mma-gather (bias+relu fused) -> h1
    k_gemm<<<tiles, 128>>>(hf, W1, yb, n);
    k_gather<true><<<gblocks, 256>>>(yb, b1, hf, n);
    // layer 2: Y2 = h1@W2, then mma-gather -> h2
    k_gemm<<<tiles, 128>>>(hf, W2, yb, n);
    k_gather<false><<<gblocks, 256>>>(yb, b2, hf, n);

    // pooling + classifier
    k_pool<<<512, 256>>>(hf, gid, n);
    k_final<<<1, 128>>>(Wc, bc, (float*)d_out, g);
}

// round 16
// speedup vs baseline: 1.5435x; 1.5435x over previous
#include <cuda_runtime.h>
#include <cuda_fp16.h>
#include <cstdint>

#define NMAX 100000
#define EMAX 3200000
#define F 64
#define GMAX 64
#define PAD 128        // bucket capacity per node (max realistic degree ~60)
#define PADSH 7
#define XSTR 72        // smem row stride in halves (144B: conflict-free ldmatrix)

struct __align__(8) EdgeT { int s; float w; };

// Scratch (device globals — no allocation allowed)
__device__ int   g_cnt_n[NMAX];                      // per-node fill cursor == degree
__device__ float g_scale[NMAX];                      // 1/(sum_w*(deg+1)), layer-1 byproduct
__device__ __align__(16) EdgeT g_csr[NMAX * PAD];    // padded buckets {src, w}
__device__ __align__(16) __half g_hf[NMAX * F];      // fp16 table A (h1 / h2)
__device__ __align__(16) __half g_y[NMAX * F];       // fp16 table B (Y = H@W)
__device__ __align__(16) float  g_pool[GMAX * F];
__device__ float g_cnt[GMAX];

__device__ __forceinline__ __half2 u2h2(unsigned u) {
    return *reinterpret_cast<__half2*>(&u);
}

// ---------------------------------------------------------------------------
// Zero cursors + pool accumulators (runs on the side stream, before fill)
// ---------------------------------------------------------------------------
__global__ void k_zero(int n, int g) {
    int i = blockIdx.x * blockDim.x + threadIdx.x;
    if (i < n) g_cnt_n[i] = 0;
    if (i < g * F) g_pool[i] = 0.f;
    if (i < g) g_cnt[i] = 0.f;
}

// ---------------------------------------------------------------------------
// Bucket fill: 8 edges per thread. Cursor atomic doubles as degree count.
// ---------------------------------------------------------------------------
__global__ void k_fill(const float* __restrict__ ew, const int* __restrict__ src,
                       const int* __restrict__ dst, int e8) {
    int i = blockIdx.x * blockDim.x + threadIdx.x;
    if (i >= e8) return;
    int4   sa = reinterpret_cast<const int4*>(src)[2 * i];
    int4   sb = reinterpret_cast<const int4*>(src)[2 * i + 1];
    int4   da = reinterpret_cast<const int4*>(dst)[2 * i];
    int4   db = reinterpret_cast<const int4*>(dst)[2 * i + 1];
    float4 wa = reinterpret_cast<const float4*>(ew)[2 * i];
    float4 wb = reinterpret_cast<const float4*>(ew)[2 * i + 1];

    int p0 = atomicAdd(&g_cnt_n[da.x], 1);
    int p1 = atomicAdd(&g_cnt_n[da.y], 1);
    int p2 = atomicAdd(&g_cnt_n[da.z], 1);
    int p3 = atomicAdd(&g_cnt_n[da.w], 1);
    int p4 = atomicAdd(&g_cnt_n[db.x], 1);
    int p5 = atomicAdd(&g_cnt_n[db.y], 1);
    int p6 = atomicAdd(&g_cnt_n[db.z], 1);
    int p7 = atomicAdd(&g_cnt_n[db.w], 1);

    EdgeT r;
    r.s = sa.x; r.w = wa.x; g_csr[(da.x << PADSH) + p0] = r;
    r.s = sa.y; r.w = wa.y; g_csr[(da.y << PADSH) + p1] = r;
    r.s = sa.z; r.w = wa.z; g_csr[(da.z << PADSH) + p2] = r;
    r.s = sa.w; r.w = wa.w; g_csr[(da.w << PADSH) + p3] = r;
    r.s = sb.x; r.w = wb.x; g_csr[(db.x << PADSH) + p4] = r;
    r.s = sb.y; r.w = wb.y; g_csr[(db.y << PADSH) + p5] = r;
    r.s = sb.z; r.w = wb.z; g_csr[(db.z << PADSH) + p6] = r;
    r.s = sb.w; r.w = wb.w; g_csr[(db.w << PADSH) + p7] = r;
}

// tail edges (e not divisible by 8)
__global__ void k_fill_tail(const float* __restrict__ ew, const int* __restrict__ src,
                            const int* __restrict__ dst, int lo, int e) {
    int i = lo + blockIdx.x * blockDim.x + threadIdx.x;
    if (i < e) {
        int d = dst[i];
        int pos = atomicAdd(&g_cnt_n[d], 1);
        EdgeT rec;
        rec.s = src[i];
        rec.w = ew[i];
        g_csr[(d << PADSH) + pos] = rec;
    }
}

// ---------------------------------------------------------------------------
// Tensor-core GEMM: Y = X @ W (fp32 or fp16 in, fp16 out, fp32 accum,
// no bias/relu). 64x64 tile, 128 threads (4 warps x 16 rows). mma m16n8k16.
// ---------------------------------------------------------------------------
template <bool FP32IN>
__global__ void __launch_bounds__(128) k_gemm(const void* __restrict__ xin,
                                              const float* __restrict__ W,
                                              __half* __restrict__ y, int n) {
    __shared__ __half Xs[64 * XSTR];
    __shared__ __half Wsm[64 * XSTR];

    int t = threadIdx.x;
    int lane = t & 31;
    int warp = t >> 5;
    int base = blockIdx.x * 64;

    if (FP32IN) {
        const float4* xf = reinterpret_cast<const float4*>(xin);   // 4 floats; 16/row
        #pragma unroll
        for (int j = 0; j < 8; j++) {
            int f = t + 128 * j;      // 0..1023
            int nl = f >> 4;          // local node
            int k4 = f & 15;          // float4 slot
            int gn = base + nl;
            float4 v = make_float4(0.f, 0.f, 0.f, 0.f);
            if (gn < n) v = xf[gn * 16 + k4];
            __half2 lo = __floats2half2_rn(v.x, v.y);
            __half2 hi = __floats2half2_rn(v.z, v.w);
            uint2 pk;
            pk.x = *reinterpret_cast<unsigned*>(&lo);
            pk.y = *reinterpret_cast<unsigned*>(&hi);
            *reinterpret_cast<uint2*>(&Xs[nl * XSTR + k4 * 4]) = pk;
        }
    } else {
        const uint4* xh = reinterpret_cast<const uint4*>(xin);     // 8 halves; 8/row
        #pragma unroll
        for (int j = 0; j < 4; j++) {
            int f = t + 128 * j;
            int nl = f >> 3;
            int k8 = f & 7;
            int gn = base + nl;
            uint4 v = make_uint4(0u, 0u, 0u, 0u);
            if (gn < n) v = xh[gn * 8 + k8];
            *reinterpret_cast<uint4*>(&Xs[nl * XSTR + k8 * 8]) = v;
        }
    }
    #pragma unroll
    for (int j = 0; j < 8; j++) {
        int f = t + 128 * j;
        int k = f >> 4;
        int n4 = f & 15;
        float4 wv = reinterpret_cast<const float4*>(W)[k * 16 + n4];
        __half2 lo = __floats2half2_rn(wv.x, wv.y);
        __half2 hi = __floats2half2_rn(wv.z, wv.w);
        uint2 pk;
        pk.x = *reinterpret_cast<unsigned*>(&lo);
        pk.y = *reinterpret_cast<unsigned*>(&hi);
        *reinterpret_cast<uint2*>(&Wsm[k * XSTR + n4 * 4]) = pk;
    }
    __syncthreads();

    float acc[8][4];
    #pragma unroll
    for (int nt = 0; nt < 8; nt++)
        #pragma unroll
        for (int i = 0; i < 4; i++) acc[nt][i] = 0.f;

    uint32_t xs_base = (uint32_t)__cvta_generic_to_shared(Xs);
    uint32_t ws_base = (uint32_t)__cvta_generic_to_shared(Wsm);

    int arow = warp * 16 + (lane & 15);
    uint32_t a_off = xs_base + (uint32_t)(arow * XSTR * 2 + (lane >> 4) * 16);
    int brow = lane & 15;

    #pragma unroll
    for (int kit = 0; kit < 4; kit++) {
        uint32_t a0, a1, a2, a3;
        asm volatile("ldmatrix.sync.aligned.m8n8.x4.shared.b16 {%0,%1,%2,%3}, [%4];"
                     : "=r"(a0), "=r"(a1), "=r"(a2), "=r"(a3)
                     : "r"(a_off + kit * 32));
        uint32_t b_base = ws_base + (uint32_t)((kit * 16 + brow) * XSTR * 2);
        #pragma unroll
        for (int nt = 0; nt < 8; nt++) {
            uint32_t b0, b1;
            asm volatile("ldmatrix.sync.aligned.m8n8.x2.trans.shared.b16 {%0,%1}, [%2];"
                         : "=r"(b0), "=r"(b1)
                         : "r"(b_base + nt * 16));
            asm volatile("mma.sync.aligned.m16n8k16.row.col.f32.f16.f16.f32 "
                         "{%0,%1,%2,%3}, {%4,%5,%6,%7}, {%8,%9}, {%0,%1,%2,%3};"
                         : "+f"(acc[nt][0]), "+f"(acc[nt][1]),
                           "+f"(acc[nt][2]), "+f"(acc[nt][3])
                         : "r"(a0), "r"(a1), "r"(a2), "r"(a3), "r"(b0), "r"(b1));
        }
    }

    int drow = warp * 16 + (lane >> 2);
    int dcolh = (lane & 3);
    #pragma unroll
    for (int nt = 0; nt < 8; nt++) {
        int col2 = nt * 4 + dcolh;
        int gn0 = base + drow;
        int gn1 = gn0 + 8;
        if (gn0 < n) {
            __half2 p = __floats2half2_rn(acc[nt][0], acc[nt][1]);
            reinterpret_cast<unsigned*>(y)[gn0 * 32 + col2] = *reinterpret_cast<unsigned*>(&p);
        }
        if (gn1 < n) {
            __half2 p = __floats2half2_rn(acc[nt][2], acc[nt][3]);
            reinterpret_cast<unsigned*>(y)[gn1 * 32 + col2] = *reinterpret_cast<unsigned*>(&p);
        }
    }
}

// ---------------------------------------------------------------------------
// Gather on Y (proven R13/R14 form): warp per dst node, 2 edges per iteration
// via half-warps, lane covers 4 features (uint2), fp32 FMA. Epilogue applies
// bias + relu and writes the fp16 table for the next stage:
//   out[node] = relu( sc * sum_e w_e*Y[src_e] + Y[node]/(deg+1) + b )
// FIRST: accumulate sum_w, store g_scale[node] = 1/(sum_w*(deg+1)).
// ---------------------------------------------------------------------------
template <bool FIRST>
__global__ void __launch_bounds__(256) k_gather(const __half* __restrict__ ytab,
                                                const float* __restrict__ b,
                                                __half* __restrict__ out, int n) {
    int w = (blockIdx.x * blockDim.x + threadIdx.x) >> 5;
    int l = threadIdx.x & 31;
    if (w >= n) return;

    int half = l >> 4;          // 0: even edges, 1: odd edges
    int fl = l & 15;            // feature group: features 4*fl .. 4*fl+3

    int cnt = g_cnt_n[w];
    const EdgeT* row = g_csr + (w << PADSH);
    const uint2* hh2 = reinterpret_cast<const uint2*>(ytab);  // 4 halves; 16 per node

    float a0 = 0.f, a1 = 0.f, a2 = 0.f, a3 = 0.f, sw = 0.f;

    int s = 0;  // slot s covers edges 2s (half 0) and 2s+1 (half 1)
    for (; 2 * (s + 4) <= cnt; s += 4) {
        EdgeT ed[4];
        #pragma unroll
        for (int j = 0; j < 4; j++) ed[j] = row[2 * (s + j) + half];
        uint2 f[4];
        #pragma unroll
        for (int j = 0; j < 4; j++) f[j] = hh2[ed[j].s * 16 + fl];
        #pragma unroll
        for (int j = 0; j < 4; j++) {
            float2 lo = __half22float2(u2h2(f[j].x));
            float2 hi = __half22float2(u2h2(f[j].y));
            float ww = ed[j].w;
            a0 = fmaf(ww, lo.x, a0);
            a1 = fmaf(ww, lo.y, a1);
            a2 = fmaf(ww, hi.x, a2);
            a3 = fmaf(ww, hi.y, a3);
            if (FIRST) sw += ww;
        }
    }
    for (int e = 2 * s + half; e < cnt; e += 2) {
        EdgeT ed = row[e];
        uint2 f = hh2[ed.s * 16 + fl];
        float2 lo = __half22float2(u2h2(f.x));
        float2 hi = __half22float2(u2h2(f.y));
        float ww = ed.w;
        a0 = fmaf(ww, lo.x, a0);
        a1 = fmaf(ww, lo.y, a1);
        a2 = fmaf(ww, hi.x, a2);
        a3 = fmaf(ww, hi.y, a3);
        if (FIRST) sw += ww;
    }

    a0 += __shfl_down_sync(0xffffffffu, a0, 16);
    a1 += __shfl_down_sync(0xffffffffu, a1, 16);
    a2 += __shfl_down_sync(0xffffffffu, a2, 16);
    a3 += __shfl_down_sync(0xffffffffu, a3, 16);
    if (FIRST) sw += __shfl_down_sync(0xffffffffu, sw, 16);

    if (l < 16) {
        float inv = 1.0f / ((float)cnt + 1.0f);
        float sc;
        if (FIRST) {
            sc = (cnt > 0) ? (inv / sw) : 0.f;
            if (l == 0) g_scale[w] = sc;
        } else {
            sc = g_scale[w];
        }

        uint2 yself = hh2[w * 16 + fl];
        float2 slo = __half22float2(u2h2(yself.x));
        float2 shi = __half22float2(u2h2(yself.y));
        float4 bv = reinterpret_cast<const float4*>(b)[fl];

        float o0 = fmaxf(fmaf(a0, sc, fmaf(slo.x, inv, bv.x)), 0.f);
        float o1 = fmaxf(fmaf(a1, sc, fmaf(slo.y, inv, bv.y)), 0.f);
        float o2 = fmaxf(fmaf(a2, sc, fmaf(shi.x, inv, bv.z)), 0.f);
        float o3 = fmaxf(fmaf(a3, sc, fmaf(shi.y, inv, bv.w)), 0.f);

        __half2 p0 = __floats2half2_rn(o0, o1);
        __half2 p1 = __floats2half2_rn(o2, o3);
        uint2 pk;
        pk.x = *reinterpret_cast<unsigned*>(&p0);
        pk.y = *reinterpret_cast<unsigned*>(&p1);
        reinterpret_cast<uint2*>(out)[w * 16 + fl] = pk;
    }
}

// ---------------------------------------------------------------------------
// Graph pooling on fp16 table: graph_ids sorted -> register run accumulation.
// ---------------------------------------------------------------------------
__global__ void k_pool(const __half* __restrict__ h, const int* __restrict__ gid, int n) {
    int wid = (blockIdx.x * blockDim.x + threadIdx.x) >> 5;
    int lane = threadIdx.x & 31;
    int nwarps = (gridDim.x * blockDim.x) >> 5;
    int chunk = (n + nwarps - 1) / nwarps;
    int start = wid * chunk;
    int end = min(start + chunk, n);
    if (start >= end) return;

    const unsigned* hp = reinterpret_cast<const unsigned*>(h);

    int cur = -1;
    float s0 = 0.f, s1 = 0.f, c = 0.f;
    for (int node = start; node < end; node++) {
        int g = gid[node];
        if (g != cur) {
            if (cur >= 0) {
                atomicAdd(&g_pool[cur * F + 2 * lane], s0);
                atomicAdd(&g_pool[cur * F + 2 * lane + 1], s1);
                if (lane == 0) atomicAdd(&g_cnt[cur], c);
            }
            cur = g; s0 = s1 = 0.f; c = 0.f;
        }
        float2 v = __half22float2(u2h2(hp[node * 32 + lane]));
        s0 += v.x;
        s1 += v.y;
        c += 1.f;
    }
    if (cur >= 0) {
        atomicAdd(&g_pool[cur * F + 2 * lane], s0);
        atomicAdd(&g_pool[cur * F + 2 * lane + 1], s1);
        if (lane == 0) atomicAdd(&g_cnt[cur], c);
    }
}

// ---------------------------------------------------------------------------
__global__ void k_final(const float* __restrict__ Wc, const float* __restrict__ bc,
                        float* __restrict__ out, int g) {
    int t = threadIdx.x;
    if (t >= g * 2) return;
    int gi = t >> 1;
    int c = t & 1;
    float inv = 1.0f / fmaxf(g_cnt[gi], 1.0f);
    float s = bc[c];
    #pragma unroll
    for (int f = 0; f < F; f++)
        s = fmaf(g_pool[gi * F + f] * inv, Wc[f * 2 + c], s);
    out[t] = s;
}

// ---------------------------------------------------------------------------
extern "C" void kernel_launch(void* const* d_in, const int* in_sizes, int n_in,
                              void* d_out, int out_size) {
    const float* in_feat = (const float*)d_in[0];
    const float* ew      = (const float*)d_in[1];
    const float* W1      = (const float*)d_in[2];
    const float* b1      = (const float*)d_in[3];
    const float* W2      = (const float*)d_in[4];
    const float* b2      = (const float*)d_in[5];
    const float* Wc      = (const float*)d_in[6];
    const float* bc      = (const float*)d_in[7];
    const int*   src     = (const int*)d_in[8];
    const int*   dst     = (const int*)d_in[9];
    const int*   gid     = (const int*)d_in[10];

    int n = in_sizes[0] / F;
    int e = in_sizes[1];
    int g = out_size / 2;

    void *p_hf = nullptr, *p_y = nullptr;
    cudaGetSymbolAddress(&p_hf, g_hf);
    cudaGetSymbolAddress(&p_y, g_y);
    __half* hf = (__half*)p_hf;
    __half* yb = (__half*)p_y;

    int e8 = e >> 3;
    int nwb = (n * 32 + 255) / 256;     // warp-per-node
    int tiles = (n + 63) / 64;

    // Side stream for the CSR build (independent of the GEMM path).
    // Created per call (kernel_launch runs ~twice: correctness + capture);
    // never destroyed to stay capture-safe. No device memory involved.
    cudaStream_t sB;
    cudaEvent_t evRoot, evB;
    cudaStreamCreateWithFlags(&sB, cudaStreamNonBlocking);
    cudaEventCreateWithFlags(&evRoot, cudaEventDisableTiming);
    cudaEventCreateWithFlags(&evB, cudaEventDisableTiming);

    // fork: side stream builds the CSR while the main stream runs gemm1
    cudaEventRecord(evRoot, 0);
    cudaStreamWaitEvent(sB, evRoot, 0);
    k_zero<<<(n + 255) / 256, 256, 0, sB>>>(n, g);
    k_fill<<<(e8 + 255) / 256, 256, 0, sB>>>(ew, src, dst, e8);
    if (e & 7)
        k_fill_tail<<<1, 256, 0, sB>>>(ew, src, dst, e8 * 8, e);
    cudaEventRecord(evB, sB);

    // main stream: layer-1 GEMM straight from fp32 in_feat (no cvt pass)
    k_gemm<true><<<tiles, 128>>>(in_feat, W1, yb, n);

    // join: gather1 needs both the CSR and Y1
    cudaStreamWaitEvent(0, evB, 0);
    k_gather<true><<<nwb, 256>>>(yb, b1, hf, n);
    // layer 2
    k_gemm<false><<<tiles, 128>>>(hf, W2, yb, n);
    k_gather<false><<<nwb, 256>>>(yb, b2, hf, n);

    // pooling + classifier
    k_pool<<<512, 256>>>(hf, gid, n);
    k_final<<<1, 128>>>(Wc, bc, (float*)d_out, g);
}